// round 12
// baseline (speedup 1.0000x reference)
#include <cuda_runtime.h>
#include <cstdint>

// ---------------------------------------------------------------- constants
#define Bc   128
#define Sc   512
#define Dc   768
#define Hc   12
#define DHc  64
#define NTOK (Bc * Sc)    // 65536
#define NH   (Sc * Hc)    // 6144
#define E3   (3 * Dc)     // 2304

// Scratch (allocation-free rule -> device globals)
__device__ float g_qkv[(size_t)NH * 3 * Bc * DHc];   // [n][qkv][b][dh], tf32 bits
__device__ float g_ctx[(size_t)NTOK * Dc];           // [b][s][d], tf32 bits
__device__ float g_Xc[(size_t)NTOK * Dc];            // tf32(X)
__device__ float g_Wq[(size_t)E3 * Dc];              // tf32(W_qkv)
__device__ float g_Wd[(size_t)Dc * Dc];              // tf32(W_dense)

// ---------------------------------------------------------------- helpers
__device__ __forceinline__ uint32_t f2tf32(float x) {
    uint32_t r;
    asm("cvt.rna.tf32.f32 %0, %1;" : "=r"(r) : "f"(x));
    return r;
}

__device__ __forceinline__ void mma_tf32(float* c, const uint32_t* a,
                                         const uint32_t* b)
{
    asm volatile(
        "mma.sync.aligned.m16n8k8.row.col.f32.tf32.tf32.f32 "
        "{%0,%1,%2,%3}, {%4,%5,%6,%7}, {%8,%9}, {%0,%1,%2,%3};"
        : "+f"(c[0]), "+f"(c[1]), "+f"(c[2]), "+f"(c[3])
        : "r"(a[0]), "r"(a[1]), "r"(a[2]), "r"(a[3]),
          "r"(b[0]), "r"(b[1]));
}

__device__ __forceinline__ uint32_t smem_u32(const void* p) {
    uint32_t a;
    asm("{ .reg .u64 t; cvta.to.shared.u64 t, %1; cvt.u32.u64 %0, t; }"
        : "=r"(a) : "l"(p));
    return a;
}
__device__ __forceinline__ void cp_async16(uint32_t dst, const void* src) {
    asm volatile("cp.async.cg.shared.global [%0], [%1], 16;"
                 :: "r"(dst), "l"(src));
}
#define CP_COMMIT() asm volatile("cp.async.commit_group;" ::: "memory")
#define CP_WAIT2()  asm volatile("cp.async.wait_group 2;" ::: "memory")

// ---------------------------------------------------------------- prep
__global__ __launch_bounds__(256) void prep_cvt(const float4* __restrict__ src,
                                                int n4, int which)
{
    float4* dst = (which == 0) ? (float4*)g_Xc
                : (which == 1) ? (float4*)g_Wq : (float4*)g_Wd;
    int i = blockIdx.x * blockDim.x + threadIdx.x;
    if (i < n4) {
        float4 v = src[i];
        v.x = __uint_as_float(f2tf32(v.x));
        v.y = __uint_as_float(f2tf32(v.y));
        v.z = __uint_as_float(f2tf32(v.z));
        v.w = __uint_as_float(f2tf32(v.w));
        dst[i] = v;
    }
}

// ---------------------------------------------------------------- tc GEMM
// C[M,N] = A[M,K] * W[N,K]^T; inputs pre-tf32-rounded.
// CTA 128x128, 128 threads = 4 warps (2x2), warp tile 64x64.
// BK=16, 4-stage cp.async, SSTR=20 conflict-free, 1 barrier/chunk.
#define BK    16
#define SSTR  20
#define TSZ   (128 * SSTR)                 // 2560 words / tile
#define SMEM_GEMM (8 * TSZ * 4)            // 81920 B

template <int MODE>
__global__ __launch_bounds__(128, 2) void gemm_mma(
    const float* __restrict__ bias, float* __restrict__ Cout,
    int K, int N)
{
    extern __shared__ uint32_t dynsm[];
    uint32_t* As = dynsm;                  // [4][TSZ]
    uint32_t* Ws = dynsm + 4 * TSZ;        // [4][TSZ]

    const float* Ap = (MODE == 1) ? (const float*)g_ctx : (const float*)g_Xc;
    const float* Wp = (MODE == 1) ? (const float*)g_Wd  : (const float*)g_Wq;

    const int tid  = threadIdx.x;
    const int lane = tid & 31;
    const int warp = tid >> 5;          // 0..3
    const int wm   = warp & 1;          // row 64-block
    const int wn   = warp >> 1;         // col 64-block
    const int g    = lane >> 2;
    const int t4   = lane & 3;

    const int rowBase = blockIdx.y * 128;
    const int colBase = blockIdx.x * 128;

    // loader: each of 128 threads owns one row (16 floats = 4x cp16)
    const int lr = tid;
    const float* gA = Ap + (size_t)(rowBase + lr) * K;
    const float* gW = Wp + (size_t)(colBase + lr) * K;

    const uint32_t sA = smem_u32(As) + (uint32_t)(lr * SSTR) * 4;
    const uint32_t sW = smem_u32(Ws) + (uint32_t)(lr * SSTR) * 4;

    const int nch = K / BK;   // 48

#pragma unroll
    for (int p = 0; p < 3; p++) {
        uint32_t da = sA + (uint32_t)(p * TSZ) * 4;
        uint32_t dw = sW + (uint32_t)(p * TSZ) * 4;
        const float* ga = gA + p * BK;
        const float* gw = gW + p * BK;
#pragma unroll
        for (int w = 0; w < 4; w++) {
            cp_async16(da + w * 16, ga + w * 4);
            cp_async16(dw + w * 16, gw + w * 4);
        }
        CP_COMMIT();
    }

    float acc[4][8][4];
#pragma unroll
    for (int i = 0; i < 4; i++)
#pragma unroll
        for (int j = 0; j < 8; j++)
#pragma unroll
            for (int k = 0; k < 4; k++) acc[i][j][k] = 0.f;

    for (int ch = 0; ch < nch; ch++) {
        CP_WAIT2();
        __syncthreads();

        if (ch + 3 < nch) {
            int st = (ch + 3) & 3;
            uint32_t da = sA + (uint32_t)(st * TSZ) * 4;
            uint32_t dw = sW + (uint32_t)(st * TSZ) * 4;
            const float* ga = gA + (ch + 3) * BK;
            const float* gw = gW + (ch + 3) * BK;
#pragma unroll
            for (int w = 0; w < 4; w++) {
                cp_async16(da + w * 16, ga + w * 4);
                cp_async16(dw + w * 16, gw + w * 4);
            }
        }
        CP_COMMIT();

        const uint32_t* Ab = As + (ch & 3) * TSZ;
        const uint32_t* Wb = Ws + (ch & 3) * TSZ;
#pragma unroll
        for (int ks = 0; ks < 2; ks++) {
            const int k0 = ks * 8;
            uint32_t af[4][4], bf[8][2];
#pragma unroll
            for (int mt = 0; mt < 4; mt++) {
                int r0 = wm * 64 + mt * 16 + g;
                af[mt][0] = Ab[(r0)     * SSTR + k0 + t4];
                af[mt][1] = Ab[(r0 + 8) * SSTR + k0 + t4];
                af[mt][2] = Ab[(r0)     * SSTR + k0 + t4 + 4];
                af[mt][3] = Ab[(r0 + 8) * SSTR + k0 + t4 + 4];
            }
#pragma unroll
            for (int nt = 0; nt < 8; nt++) {
                int c0 = wn * 64 + nt * 8 + g;
                bf[nt][0] = Wb[c0 * SSTR + k0 + t4];
                bf[nt][1] = Wb[c0 * SSTR + k0 + t4 + 4];
            }
#pragma unroll
            for (int mt = 0; mt < 4; mt++)
#pragma unroll
                for (int nt = 0; nt < 8; nt++)
                    mma_tf32(acc[mt][nt], af[mt], bf[nt]);
        }
    }

    // ---- epilogue ----
#pragma unroll
    for (int mt = 0; mt < 4; mt++) {
#pragma unroll
        for (int nt = 0; nt < 8; nt++) {
#pragma unroll
            for (int hi = 0; hi < 2; hi++) {
                int r = rowBase + wm * 64 + mt * 16 + g + hi * 8;
                int c = colBase + wn * 64 + nt * 8 + 2 * t4;
                float v0 = acc[mt][nt][hi * 2 + 0];
                float v1 = acc[mt][nt][hi * 2 + 1];
                if (MODE == 0) {
                    int b  = r >> 9;
                    int ss = r & 511;
#pragma unroll
                    for (int q = 0; q < 2; q++) {
                        int e = c + q;
                        float v = (q ? v1 : v0) + bias[e];
                        int h = e / 192, rr = e - h * 192;
                        int w = rr >> 6, dh = rr & 63;
                        int n = ss * Hc + h;
                        g_qkv[(((size_t)n * 3 + w) * Bc + b) * DHc + dh] =
                            __uint_as_float(f2tf32(v));
                    }
                } else {
                    float2* dst = (float2*)(Cout + (size_t)r * N + c);
                    *dst = make_float2(v0, v1);
                }
            }
        }
    }
}

// ---------------------------------------------------------------- attention
// (unchanged — validated)
#define QP 68
#define PP 132
#define OFF_KS (128 * QP)
#define OFF_VT (2 * 128 * QP)
#define ATTN_FLOATS (OFF_VT + 64 * PP)
#define SMEM_ATTN (ATTN_FLOATS * 4)

__global__ __launch_bounds__(256, 1) void attn_kernel()
{
    extern __shared__ float sm[];
    uint32_t* Qs = (uint32_t*)sm;
    uint32_t* Ks = (uint32_t*)sm + OFF_KS;
    uint32_t* Vt = (uint32_t*)sm + OFF_VT;
    float*    Ps = sm;

    const int n   = blockIdx.x;
    const int tid = threadIdx.x;
    const int lane = tid & 31;
    const int warp = tid >> 5;
    const int wm = warp & 1;
    const int wn = warp >> 1;
    const int g  = lane >> 2;
    const int t4 = lane & 3;

    const uint32_t* qb = (const uint32_t*)(g_qkv + (size_t)n * 3 * Bc * DHc);
    const uint32_t* kb = qb + Bc * DHc;
    const uint32_t* vb = kb + Bc * DHc;

#pragma unroll
    for (int it = 0; it < 32; it++) {
        int idx = tid + it * 256;
        int r  = idx >> 6;
        int dh = idx & 63;
        Qs[r * QP + dh] = qb[idx];
        Ks[r * QP + dh] = kb[idx];
        Vt[dh * PP + r] = vb[idx];
    }
    __syncthreads();

    float acc[4][4][4];
#pragma unroll
    for (int i = 0; i < 4; i++)
#pragma unroll
        for (int j = 0; j < 4; j++)
#pragma unroll
            for (int k = 0; k < 4; k++) acc[i][j][k] = 0.f;

#pragma unroll
    for (int ks = 0; ks < 8; ks++) {
        const int k0 = ks * 8;
        uint32_t af[4][4], bf[4][2];
#pragma unroll
        for (int mt = 0; mt < 4; mt++) {
            int r0 = wm * 64 + mt * 16 + g;
            af[mt][0] = Qs[(r0)     * QP + k0 + t4];
            af[mt][1] = Qs[(r0 + 8) * QP + k0 + t4];
            af[mt][2] = Qs[(r0)     * QP + k0 + t4 + 4];
            af[mt][3] = Qs[(r0 + 8) * QP + k0 + t4 + 4];
        }
#pragma unroll
        for (int nt = 0; nt < 4; nt++) {
            int c0 = wn * 32 + nt * 8 + g;
            bf[nt][0] = Ks[c0 * QP + k0 + t4];
            bf[nt][1] = Ks[c0 * QP + k0 + t4 + 4];
        }
#pragma unroll
        for (int mt = 0; mt < 4; mt++)
#pragma unroll
            for (int nt = 0; nt < 4; nt++)
                mma_tf32(acc[mt][nt], af[mt], bf[nt]);
    }
    __syncthreads();

    const float scale = 0.125f;
#pragma unroll
    for (int mt = 0; mt < 4; mt++)
#pragma unroll
        for (int nt = 0; nt < 4; nt++)
#pragma unroll
            for (int hi = 0; hi < 2; hi++) {
                int r = wm * 64 + mt * 16 + g + hi * 8;
                int c = wn * 32 + nt * 8 + 2 * t4;
#pragma unroll
                for (int q = 0; q < 2; q++) {
                    float s = acc[mt][nt][hi * 2 + q] * scale;
                    if (c + q <= r) s = -10000.0f;
                    Ps[r * PP + c + q] = s;
                }
            }
    __syncthreads();

    for (int r = warp; r < 128; r += 8) {
        float v0 = Ps[r * PP + lane];
        float v1 = Ps[r * PP + lane + 32];
        float v2 = Ps[r * PP + lane + 64];
        float v3 = Ps[r * PP + lane + 96];
        float mx = fmaxf(fmaxf(v0, v1), fmaxf(v2, v3));
#pragma unroll
        for (int o = 16; o > 0; o >>= 1)
            mx = fmaxf(mx, __shfl_xor_sync(0xffffffffu, mx, o));
        float e0 = __expf(v0 - mx), e1 = __expf(v1 - mx);
        float e2 = __expf(v2 - mx), e3 = __expf(v3 - mx);
        float sum = e0 + e1 + e2 + e3;
#pragma unroll
        for (int o = 16; o > 0; o >>= 1)
            sum += __shfl_xor_sync(0xffffffffu, sum, o);
        float inv = 1.0f / sum;
        Ps[r * PP + lane]      = __uint_as_float(f2tf32(e0 * inv));
        Ps[r * PP + lane + 32] = __uint_as_float(f2tf32(e1 * inv));
        Ps[r * PP + lane + 64] = __uint_as_float(f2tf32(e2 * inv));
        Ps[r * PP + lane + 96] = __uint_as_float(f2tf32(e3 * inv));
    }
    __syncthreads();

    const uint32_t* Pu = (const uint32_t*)Ps;
    float acc2[4][2][4];
#pragma unroll
    for (int i = 0; i < 4; i++)
#pragma unroll
        for (int j = 0; j < 2; j++)
#pragma unroll
            for (int k = 0; k < 4; k++) acc2[i][j][k] = 0.f;

#pragma unroll
    for (int ks = 0; ks < 16; ks++) {
        const int k0 = ks * 8;
        uint32_t af[4][4], bf[2][2];
#pragma unroll
        for (int mt = 0; mt < 4; mt++) {
            int r0 = wm * 64 + mt * 16 + g;
            af[mt][0] = Pu[(r0)     * PP + k0 + t4];
            af[mt][1] = Pu[(r0 + 8) * PP + k0 + t4];
            af[mt][2] = Pu[(r0)     * PP + k0 + t4 + 4];
            af[mt][3] = Pu[(r0 + 8) * PP + k0 + t4 + 4];
        }
#pragma unroll
        for (int nt = 0; nt < 2; nt++) {
            int c0 = wn * 16 + nt * 8 + g;
            bf[nt][0] = Vt[c0 * PP + k0 + t4];
            bf[nt][1] = Vt[c0 * PP + k0 + t4 + 4];
        }
#pragma unroll
        for (int mt = 0; mt < 4; mt++)
#pragma unroll
            for (int nt = 0; nt < 2; nt++)
                mma_tf32(acc2[mt][nt], af[mt], bf[nt]);
    }

    const int s = n / Hc;
    const int h = n - s * Hc;
#pragma unroll
    for (int mt = 0; mt < 4; mt++)
#pragma unroll
        for (int nt = 0; nt < 2; nt++)
#pragma unroll
            for (int hi = 0; hi < 2; hi++) {
                int b  = wm * 64 + mt * 16 + g + hi * 8;
                int dh = wn * 16 + nt * 8 + 2 * t4;
                float2* dst = (float2*)(g_ctx +
                    ((size_t)b * Sc + s) * Dc + h * 64 + dh);
                *dst = make_float2(
                    __uint_as_float(f2tf32(acc2[mt][nt][hi * 2 + 0])),
                    __uint_as_float(f2tf32(acc2[mt][nt][hi * 2 + 1])));
            }
}

// ----------------------------------------------------------------
extern "C" void kernel_launch(void* const* d_in, const int* in_sizes, int n_in,
                              void* d_out, int out_size)
{
    const float* X       = (const float*)d_in[0];
    const float* W_qkv   = (const float*)d_in[1];
    const float* b_qkv   = (const float*)d_in[2];
    const float* W_dense = (const float*)d_in[3];
    const float* b_dense = (const float*)d_in[4];
    float* out = (float*)d_out;
    (void)in_sizes; (void)n_in;

    cudaFuncSetAttribute(gemm_mma<0>,
                         cudaFuncAttributeMaxDynamicSharedMemorySize, SMEM_GEMM);
    cudaFuncSetAttribute(gemm_mma<1>,
                         cudaFuncAttributeMaxDynamicSharedMemorySize, SMEM_GEMM);
    cudaFuncSetAttribute(attn_kernel,
                         cudaFuncAttributeMaxDynamicSharedMemorySize, SMEM_ATTN);

    // 0) one-time tf32 rounding passes
    {
        int n4x = NTOK * Dc / 4;
        prep_cvt<<<(n4x + 255) / 256, 256>>>((const float4*)X, n4x, 0);
        int n4q = E3 * Dc / 4;
        prep_cvt<<<(n4q + 255) / 256, 256>>>((const float4*)W_qkv, n4q, 1);
        int n4d = Dc * Dc / 4;
        prep_cvt<<<(n4d + 255) / 256, 256>>>((const float4*)W_dense, n4d, 2);
    }

    // 1) QKV = tf32(X) @ tf32(W_qkv)^T + bias -> g_qkv (tf32 bits)
    gemm_mma<0><<<dim3(E3 / 128, NTOK / 128), 128, SMEM_GEMM>>>(
        b_qkv, nullptr, Dc, E3);

    // 2) attention
    attn_kernel<<<NH, 256, SMEM_ATTN>>>();

    // 3) out = ctx @ tf32(W_dense)^T
    gemm_mma<1><<<dim3(Dc / 128, NTOK / 128), 128, SMEM_GEMM>>>(
        nullptr, out, Dc, Dc);

    // 4) tail: reference returns (out, b_dense)
    long long tail = (long long)out_size - (long long)NTOK * Dc;
    if (tail > 0) {
        if (tail > Dc) tail = Dc;
        cudaMemcpyAsync(out + (size_t)NTOK * Dc, b_dense,
                        (size_t)tail * sizeof(float),
                        cudaMemcpyDeviceToDevice, 0);
    }
}

// round 14
// speedup vs baseline: 1.2116x; 1.2116x over previous
#include <cuda_runtime.h>
#include <cstdint>

// ---------------------------------------------------------------- constants
#define Bc   128
#define Sc   512
#define Dc   768
#define Hc   12
#define DHc  64
#define NTOK (Bc * Sc)    // 65536
#define NH   (Sc * Hc)    // 6144
#define E3   (3 * Dc)     // 2304

// Scratch (allocation-free rule -> device globals)
__device__ float g_qkv[(size_t)NH * 3 * Bc * DHc];   // [n][qkv][b][dh], tf32 bits
__device__ float g_ctx[(size_t)NTOK * Dc];           // [b][s][d], tf32 bits
__device__ float g_Xc[(size_t)NTOK * Dc];            // tf32(X)
__device__ float g_Wq[(size_t)E3 * Dc];              // tf32(W_qkv)
__device__ float g_Wd[(size_t)Dc * Dc];              // tf32(W_dense)

// ---------------------------------------------------------------- helpers
__device__ __forceinline__ uint32_t f2tf32(float x) {
    uint32_t r;
    asm("cvt.rna.tf32.f32 %0, %1;" : "=r"(r) : "f"(x));
    return r;
}

__device__ __forceinline__ void mma_tf32(float* c, const uint32_t* a,
                                         const uint32_t* b)
{
    asm volatile(
        "mma.sync.aligned.m16n8k8.row.col.f32.tf32.tf32.f32 "
        "{%0,%1,%2,%3}, {%4,%5,%6,%7}, {%8,%9}, {%0,%1,%2,%3};"
        : "+f"(c[0]), "+f"(c[1]), "+f"(c[2]), "+f"(c[3])
        : "r"(a[0]), "r"(a[1]), "r"(a[2]), "r"(a[3]),
          "r"(b[0]), "r"(b[1]));
}

__device__ __forceinline__ uint32_t smem_u32(const void* p) {
    uint32_t a;
    asm("{ .reg .u64 t; cvta.to.shared.u64 t, %1; cvt.u32.u64 %0, t; }"
        : "=r"(a) : "l"(p));
    return a;
}
__device__ __forceinline__ void cp_async16(uint32_t dst, const void* src) {
    asm volatile("cp.async.cg.shared.global [%0], [%1], 16;"
                 :: "r"(dst), "l"(src));
}
#define CP_COMMIT() asm volatile("cp.async.commit_group;" ::: "memory")
#define CP_WAIT1()  asm volatile("cp.async.wait_group 1;" ::: "memory")

// ---------------------------------------------------------------- prep
__global__ __launch_bounds__(256) void prep_cvt(const float4* __restrict__ src,
                                                int n4, int which)
{
    float4* dst = (which == 0) ? (float4*)g_Xc
                : (which == 1) ? (float4*)g_Wq : (float4*)g_Wd;
    int i = blockIdx.x * blockDim.x + threadIdx.x;
    if (i < n4) {
        float4 v = src[i];
        v.x = __uint_as_float(f2tf32(v.x));
        v.y = __uint_as_float(f2tf32(v.y));
        v.z = __uint_as_float(f2tf32(v.z));
        v.w = __uint_as_float(f2tf32(v.w));
        dst[i] = v;
    }
}

// ---------------------------------------------------------------- tc GEMM
// C[M,N] = A[M,K] * W[N,K]^T; inputs pre-tf32-rounded.
// CTA 128x128, 256 threads (8 warps, 2x4, warp tile 64x32), BK=16.
// 5-stage cp.async ring; __syncthreads every 2 chunks (warps desync by
// up to one chunk -> LDS/tensor phase overlap across warps).
#define BK    16
#define SSTR  20
#define TSZ   (128 * SSTR)                 // 2560 words / tile (10KB)
#define NSTG  5
#define SMEM_GEMM (NSTG * 2 * TSZ * 4)     // 102400 B

template <int MODE>
__global__ __launch_bounds__(256, 2) void gemm_mma(
    const float* __restrict__ bias, float* __restrict__ Cout,
    int K, int N)
{
    extern __shared__ uint32_t dynsm[];    // [NSTG][2][TSZ] (A then W)

    const float* Ap = (MODE == 1) ? (const float*)g_ctx : (const float*)g_Xc;
    const float* Wp = (MODE == 1) ? (const float*)g_Wd  : (const float*)g_Wq;

    const int tid  = threadIdx.x;
    const int lane = tid & 31;
    const int warp = tid >> 5;
    const int wm   = warp & 1;
    const int wn   = warp >> 1;
    const int g    = lane >> 2;
    const int t4   = lane & 3;

    const int rowBase = blockIdx.y * 128;
    const int colBase = blockIdx.x * 128;

    const int lr = tid >> 1;
    const int lc = (tid & 1) * 8;

    const float* gA = Ap + (size_t)(rowBase + lr) * K + lc;
    const float* gW = Wp + (size_t)(colBase + lr) * K + lc;

    const uint32_t sBase = smem_u32(dynsm) + (uint32_t)(lr * SSTR + lc) * 4;

    const int nch = K / BK;   // 48 (even)

    auto issue = [&](int ch) {
        int st = ch % NSTG;
        uint32_t da = sBase + (uint32_t)(st * 2 * TSZ) * 4;
        uint32_t dw = da + (uint32_t)TSZ * 4;
        const float* ga = gA + ch * BK;
        const float* gw = gW + ch * BK;
        cp_async16(da,      ga);
        cp_async16(da + 16, ga + 4);
        cp_async16(dw,      gw);
        cp_async16(dw + 16, gw + 4);
    };

    // prologue: chunks 0,1,2 -> stages 0,1,2
#pragma unroll
    for (int p = 0; p < 3; p++) { issue(p); CP_COMMIT(); }

    float acc[4][4][4];
#pragma unroll
    for (int i = 0; i < 4; i++)
#pragma unroll
        for (int j = 0; j < 4; j++)
#pragma unroll
            for (int k = 0; k < 4; k++) acc[i][j][k] = 0.f;

    auto compute = [&](int ch) {
        const uint32_t* Ab = dynsm + (ch % NSTG) * 2 * TSZ;
        const uint32_t* Wb = Ab + TSZ;
#pragma unroll
        for (int ks = 0; ks < 2; ks++) {
            const int k0 = ks * 8;
            uint32_t af[4][4], bf[4][2];
#pragma unroll
            for (int mt = 0; mt < 4; mt++) {
                int r0 = wm * 64 + mt * 16 + g;
                af[mt][0] = Ab[(r0)     * SSTR + k0 + t4];
                af[mt][1] = Ab[(r0 + 8) * SSTR + k0 + t4];
                af[mt][2] = Ab[(r0)     * SSTR + k0 + t4 + 4];
                af[mt][3] = Ab[(r0 + 8) * SSTR + k0 + t4 + 4];
            }
#pragma unroll
            for (int nt = 0; nt < 4; nt++) {
                int c0 = wn * 32 + nt * 8 + g;
                bf[nt][0] = Wb[c0 * SSTR + k0 + t4];
                bf[nt][1] = Wb[c0 * SSTR + k0 + t4 + 4];
            }
#pragma unroll
            for (int mt = 0; mt < 4; mt++)
#pragma unroll
                for (int nt = 0; nt < 4; nt++)
                    mma_tf32(acc[mt][nt], af[mt], bf[nt]);
        }
    };

    for (int ch = 0; ch < nch; ch += 2) {
        // both chunks ch and ch+1 resident for ALL threads after this pair
        CP_WAIT1();
        __syncthreads();

        // chunk ch
        if (ch + 3 < nch) issue(ch + 3);
        CP_COMMIT();
        compute(ch);

        // chunk ch+1 (no barrier -> warps desync up to one chunk)
        if (ch + 4 < nch) issue(ch + 4);
        CP_COMMIT();
        compute(ch + 1);
    }

    // ---- epilogue (R8-validated) ----
#pragma unroll
    for (int mt = 0; mt < 4; mt++) {
#pragma unroll
        for (int nt = 0; nt < 4; nt++) {
#pragma unroll
            for (int hi = 0; hi < 2; hi++) {
                int r = rowBase + wm * 64 + mt * 16 + g + hi * 8;
                int c = colBase + wn * 32 + nt * 8 + 2 * t4;
                float v0 = acc[mt][nt][hi * 2 + 0];
                float v1 = acc[mt][nt][hi * 2 + 1];
                if (MODE == 0) {
                    int b  = r >> 9;
                    int ss = r & 511;
#pragma unroll
                    for (int q = 0; q < 2; q++) {
                        int e = c + q;
                        float v = (q ? v1 : v0) + bias[e];
                        int h = e / 192, rr = e - h * 192;
                        int w = rr >> 6, dh = rr & 63;
                        int n = ss * Hc + h;
                        g_qkv[(((size_t)n * 3 + w) * Bc + b) * DHc + dh] =
                            __uint_as_float(f2tf32(v));
                    }
                } else {
                    float2* dst = (float2*)(Cout + (size_t)r * N + c);
                    *dst = make_float2(v0, v1);
                }
            }
        }
    }
}

// ---------------------------------------------------------------- attention
// (unchanged — validated)
#define QP 68
#define PP 132
#define OFF_KS (128 * QP)
#define OFF_VT (2 * 128 * QP)
#define ATTN_FLOATS (OFF_VT + 64 * PP)
#define SMEM_ATTN (ATTN_FLOATS * 4)

__global__ __launch_bounds__(256, 1) void attn_kernel()
{
    extern __shared__ float sm[];
    uint32_t* Qs = (uint32_t*)sm;
    uint32_t* Ks = (uint32_t*)sm + OFF_KS;
    uint32_t* Vt = (uint32_t*)sm + OFF_VT;
    float*    Ps = sm;

    const int n   = blockIdx.x;
    const int tid = threadIdx.x;
    const int lane = tid & 31;
    const int warp = tid >> 5;
    const int wm = warp & 1;
    const int wn = warp >> 1;
    const int g  = lane >> 2;
    const int t4 = lane & 3;

    const uint32_t* qb = (const uint32_t*)(g_qkv + (size_t)n * 3 * Bc * DHc);
    const uint32_t* kb = qb + Bc * DHc;
    const uint32_t* vb = kb + Bc * DHc;

#pragma unroll
    for (int it = 0; it < 32; it++) {
        int idx = tid + it * 256;
        int r  = idx >> 6;
        int dh = idx & 63;
        Qs[r * QP + dh] = qb[idx];
        Ks[r * QP + dh] = kb[idx];
        Vt[dh * PP + r] = vb[idx];
    }
    __syncthreads();

    float acc[4][4][4];
#pragma unroll
    for (int i = 0; i < 4; i++)
#pragma unroll
        for (int j = 0; j < 4; j++)
#pragma unroll
            for (int k = 0; k < 4; k++) acc[i][j][k] = 0.f;

#pragma unroll
    for (int ks = 0; ks < 8; ks++) {
        const int k0 = ks * 8;
        uint32_t af[4][4], bf[4][2];
#pragma unroll
        for (int mt = 0; mt < 4; mt++) {
            int r0 = wm * 64 + mt * 16 + g;
            af[mt][0] = Qs[(r0)     * QP + k0 + t4];
            af[mt][1] = Qs[(r0 + 8) * QP + k0 + t4];
            af[mt][2] = Qs[(r0)     * QP + k0 + t4 + 4];
            af[mt][3] = Qs[(r0 + 8) * QP + k0 + t4 + 4];
        }
#pragma unroll
        for (int nt = 0; nt < 4; nt++) {
            int c0 = wn * 32 + nt * 8 + g;
            bf[nt][0] = Ks[c0 * QP + k0 + t4];
            bf[nt][1] = Ks[c0 * QP + k0 + t4 + 4];
        }
#pragma unroll
        for (int mt = 0; mt < 4; mt++)
#pragma unroll
            for (int nt = 0; nt < 4; nt++)
                mma_tf32(acc[mt][nt], af[mt], bf[nt]);
    }
    __syncthreads();

    const float scale = 0.125f;
#pragma unroll
    for (int mt = 0; mt < 4; mt++)
#pragma unroll
        for (int nt = 0; nt < 4; nt++)
#pragma unroll
            for (int hi = 0; hi < 2; hi++) {
                int r = wm * 64 + mt * 16 + g + hi * 8;
                int c = wn * 32 + nt * 8 + 2 * t4;
#pragma unroll
                for (int q = 0; q < 2; q++) {
                    float s = acc[mt][nt][hi * 2 + q] * scale;
                    if (c + q <= r) s = -10000.0f;
                    Ps[r * PP + c + q] = s;
                }
            }
    __syncthreads();

    for (int r = warp; r < 128; r += 8) {
        float v0 = Ps[r * PP + lane];
        float v1 = Ps[r * PP + lane + 32];
        float v2 = Ps[r * PP + lane + 64];
        float v3 = Ps[r * PP + lane + 96];
        float mx = fmaxf(fmaxf(v0, v1), fmaxf(v2, v3));
#pragma unroll
        for (int o = 16; o > 0; o >>= 1)
            mx = fmaxf(mx, __shfl_xor_sync(0xffffffffu, mx, o));
        float e0 = __expf(v0 - mx), e1 = __expf(v1 - mx);
        float e2 = __expf(v2 - mx), e3 = __expf(v3 - mx);
        float sum = e0 + e1 + e2 + e3;
#pragma unroll
        for (int o = 16; o > 0; o >>= 1)
            sum += __shfl_xor_sync(0xffffffffu, sum, o);
        float inv = 1.0f / sum;
        Ps[r * PP + lane]      = __uint_as_float(f2tf32(e0 * inv));
        Ps[r * PP + lane + 32] = __uint_as_float(f2tf32(e1 * inv));
        Ps[r * PP + lane + 64] = __uint_as_float(f2tf32(e2 * inv));
        Ps[r * PP + lane + 96] = __uint_as_float(f2tf32(e3 * inv));
    }
    __syncthreads();

    const uint32_t* Pu = (const uint32_t*)Ps;
    float acc2[4][2][4];
#pragma unroll
    for (int i = 0; i < 4; i++)
#pragma unroll
        for (int j = 0; j < 2; j++)
#pragma unroll
            for (int k = 0; k < 4; k++) acc2[i][j][k] = 0.f;

#pragma unroll
    for (int ks = 0; ks < 16; ks++) {
        const int k0 = ks * 8;
        uint32_t af[4][4], bf[2][2];
#pragma unroll
        for (int mt = 0; mt < 4; mt++) {
            int r0 = wm * 64 + mt * 16 + g;
            af[mt][0] = Pu[(r0)     * PP + k0 + t4];
            af[mt][1] = Pu[(r0 + 8) * PP + k0 + t4];
            af[mt][2] = Pu[(r0)     * PP + k0 + t4 + 4];
            af[mt][3] = Pu[(r0 + 8) * PP + k0 + t4 + 4];
        }
#pragma unroll
        for (int nt = 0; nt < 2; nt++) {
            int c0 = wn * 16 + nt * 8 + g;
            bf[nt][0] = Vt[c0 * PP + k0 + t4];
            bf[nt][1] = Vt[c0 * PP + k0 + t4 + 4];
        }
#pragma unroll
        for (int mt = 0; mt < 4; mt++)
#pragma unroll
            for (int nt = 0; nt < 2; nt++)
                mma_tf32(acc2[mt][nt], af[mt], bf[nt]);
    }

    const int s = n / Hc;
    const int h = n - s * Hc;
#pragma unroll
    for (int mt = 0; mt < 4; mt++)
#pragma unroll
        for (int nt = 0; nt < 2; nt++)
#pragma unroll
            for (int hi = 0; hi < 2; hi++) {
                int b  = wm * 64 + mt * 16 + g + hi * 8;
                int dh = wn * 16 + nt * 8 + 2 * t4;
                float2* dst = (float2*)(g_ctx +
                    ((size_t)b * Sc + s) * Dc + h * 64 + dh);
                *dst = make_float2(
                    __uint_as_float(f2tf32(acc2[mt][nt][hi * 2 + 0])),
                    __uint_as_float(f2tf32(acc2[mt][nt][hi * 2 + 1])));
            }
}

// ----------------------------------------------------------------
extern "C" void kernel_launch(void* const* d_in, const int* in_sizes, int n_in,
                              void* d_out, int out_size)
{
    const float* X       = (const float*)d_in[0];
    const float* W_qkv   = (const float*)d_in[1];
    const float* b_qkv   = (const float*)d_in[2];
    const float* W_dense = (const float*)d_in[3];
    const float* b_dense = (const float*)d_in[4];
    float* out = (float*)d_out;
    (void)in_sizes; (void)n_in;

    cudaFuncSetAttribute(gemm_mma<0>,
                         cudaFuncAttributeMaxDynamicSharedMemorySize, SMEM_GEMM);
    cudaFuncSetAttribute(gemm_mma<1>,
                         cudaFuncAttributeMaxDynamicSharedMemorySize, SMEM_GEMM);
    cudaFuncSetAttribute(attn_kernel,
                         cudaFuncAttributeMaxDynamicSharedMemorySize, SMEM_ATTN);

    // 0) one-time tf32 rounding passes
    {
        int n4x = NTOK * Dc / 4;
        prep_cvt<<<(n4x + 255) / 256, 256>>>((const float4*)X, n4x, 0);
        int n4q = E3 * Dc / 4;
        prep_cvt<<<(n4q + 255) / 256, 256>>>((const float4*)W_qkv, n4q, 1);
        int n4d = Dc * Dc / 4;
        prep_cvt<<<(n4d + 255) / 256, 256>>>((const float4*)W_dense, n4d, 2);
    }

    // 1) QKV = tf32(X) @ tf32(W_qkv)^T + bias -> g_qkv (tf32 bits)
    gemm_mma<0><<<dim3(E3 / 128, NTOK / 128), 256, SMEM_GEMM>>>(
        b_qkv, nullptr, Dc, E3);

    // 2) attention
    attn_kernel<<<NH, 256, SMEM_ATTN>>>();

    // 3) out = ctx @ tf32(W_dense)^T
    gemm_mma<1><<<dim3(Dc / 128, NTOK / 128), 256, SMEM_GEMM>>>(
        nullptr, out, Dc, Dc);

    // 4) tail: reference returns (out, b_dense)
    long long tail = (long long)out_size - (long long)NTOK * Dc;
    if (tail > 0) {
        if (tail > Dc) tail = Dc;
        cudaMemcpyAsync(out + (size_t)NTOK * Dc, b_dense,
                        (size_t)tail * sizeof(float),
                        cudaMemcpyDeviceToDevice, 0);
    }
}

// round 15
// speedup vs baseline: 1.3657x; 1.1272x over previous
#include <cuda_runtime.h>
#include <cstdint>

// ---------------------------------------------------------------- constants
#define Bc   128
#define Sc   512
#define Dc   768
#define Hc   12
#define DHc  64
#define NTOK (Bc * Sc)    // 65536
#define NH   (Sc * Hc)    // 6144
#define E3   (3 * Dc)     // 2304

// Scratch (allocation-free rule -> device globals)
__device__ float g_qkv[(size_t)NH * 3 * Bc * DHc];   // [n][qkv][b][dh], tf32 bits
__device__ float g_ctx[(size_t)NTOK * Dc];           // [b][s][d], tf32 bits
__device__ float g_Xc[(size_t)NTOK * Dc];            // tf32(X)
__device__ float g_Wq[(size_t)E3 * Dc];              // tf32(W_qkv)
__device__ float g_Wd[(size_t)Dc * Dc];              // tf32(W_dense)

// ---------------------------------------------------------------- helpers
__device__ __forceinline__ uint32_t f2tf32(float x) {
    uint32_t r;
    asm("cvt.rna.tf32.f32 %0, %1;" : "=r"(r) : "f"(x));
    return r;
}

__device__ __forceinline__ void mma_tf32(float* c, const uint32_t* a,
                                         const uint32_t* b)
{
    asm volatile(
        "mma.sync.aligned.m16n8k8.row.col.f32.tf32.tf32.f32 "
        "{%0,%1,%2,%3}, {%4,%5,%6,%7}, {%8,%9}, {%0,%1,%2,%3};"
        : "+f"(c[0]), "+f"(c[1]), "+f"(c[2]), "+f"(c[3])
        : "r"(a[0]), "r"(a[1]), "r"(a[2]), "r"(a[3]),
          "r"(b[0]), "r"(b[1]));
}

__device__ __forceinline__ void ldsm_x4(uint32_t* r, uint32_t addr) {
    asm volatile(
        "ldmatrix.sync.aligned.m8n8.x4.shared.b16 {%0,%1,%2,%3}, [%4];"
        : "=r"(r[0]), "=r"(r[1]), "=r"(r[2]), "=r"(r[3]) : "r"(addr));
}

__device__ __forceinline__ uint32_t smem_u32(const void* p) {
    uint32_t a;
    asm("{ .reg .u64 t; cvta.to.shared.u64 t, %1; cvt.u32.u64 %0, t; }"
        : "=r"(a) : "l"(p));
    return a;
}
__device__ __forceinline__ void cp_async16(uint32_t dst, const void* src) {
    asm volatile("cp.async.cg.shared.global [%0], [%1], 16;"
                 :: "r"(dst), "l"(src));
}
#define CP_COMMIT() asm volatile("cp.async.commit_group;" ::: "memory")
#define CP_WAIT1()  asm volatile("cp.async.wait_group 1;" ::: "memory")

// ---------------------------------------------------------------- prep
__global__ __launch_bounds__(256) void prep_cvt(const float4* __restrict__ src,
                                                int n4, int which)
{
    float4* dst = (which == 0) ? (float4*)g_Xc
                : (which == 1) ? (float4*)g_Wq : (float4*)g_Wd;
    int i = blockIdx.x * blockDim.x + threadIdx.x;
    if (i < n4) {
        float4 v = src[i];
        v.x = __uint_as_float(f2tf32(v.x));
        v.y = __uint_as_float(f2tf32(v.y));
        v.z = __uint_as_float(f2tf32(v.z));
        v.w = __uint_as_float(f2tf32(v.w));
        dst[i] = v;
    }
}

// ---------------------------------------------------------------- tc GEMM
// C[M,N] = A[M,K] * W[N,K]^T; inputs pre-tf32-rounded.
// CTA 128x128, 256 threads (8 warps, 2x4, warp tile 64x32), BK=16.
// 5-stage cp.async ring, barrier every 2 chunks, ldmatrix.x4 fragment loads.
#define BK    16
#define SSTR  20
#define TSZ   (128 * SSTR)                 // 2560 words / tile (10KB)
#define NSTG  5
#define SMEM_GEMM (NSTG * 2 * TSZ * 4)     // 102400 B

template <int MODE>
__global__ __launch_bounds__(256, 2) void gemm_mma(
    const float* __restrict__ bias, float* __restrict__ Cout,
    int K, int N)
{
    extern __shared__ uint32_t dynsm[];    // [NSTG][2][TSZ] (A then W)

    const float* Ap = (MODE == 1) ? (const float*)g_ctx : (const float*)g_Xc;
    const float* Wp = (MODE == 1) ? (const float*)g_Wd  : (const float*)g_Wq;

    const int tid  = threadIdx.x;
    const int lane = tid & 31;
    const int warp = tid >> 5;
    const int wm   = warp & 1;
    const int wn   = warp >> 1;
    const int g    = lane >> 2;
    const int t4   = lane & 3;

    const int rowBase = blockIdx.y * 128;
    const int colBase = blockIdx.x * 128;

    const int lr = tid >> 1;
    const int lc = (tid & 1) * 8;

    const float* gA = Ap + (size_t)(rowBase + lr) * K + lc;
    const float* gW = Wp + (size_t)(colBase + lr) * K + lc;

    const uint32_t smBase = smem_u32(dynsm);
    const uint32_t sBase  = smBase + (uint32_t)(lr * SSTR + lc) * 4;

    // ldmatrix per-thread address offsets (words)
    // A: matrix id m = lane>>3; row-group = m&1 (+8 rows); col-group = m>>1 (+4 k)
    const int aOffW = (wm * 64 + ((lane >> 3) & 1) * 8 + (lane & 7)) * SSTR
                    + (lane >> 4) * 4;
    // B: row-group = m>>1 (+8 rows); col-group = m&1 (+4 k)
    const int bOffW = (wn * 32 + (lane >> 4) * 8 + (lane & 7)) * SSTR
                    + ((lane >> 3) & 1) * 4;

    const int nch = K / BK;   // 48 (even)

    auto issue = [&](int ch) {
        int st = ch % NSTG;
        uint32_t da = sBase + (uint32_t)(st * 2 * TSZ) * 4;
        uint32_t dw = da + (uint32_t)TSZ * 4;
        const float* ga = gA + ch * BK;
        const float* gw = gW + ch * BK;
        cp_async16(da,      ga);
        cp_async16(da + 16, ga + 4);
        cp_async16(dw,      gw);
        cp_async16(dw + 16, gw + 4);
    };

#pragma unroll
    for (int p = 0; p < 3; p++) { issue(p); CP_COMMIT(); }

    float acc[4][4][4];
#pragma unroll
    for (int i = 0; i < 4; i++)
#pragma unroll
        for (int j = 0; j < 4; j++)
#pragma unroll
            for (int k = 0; k < 4; k++) acc[i][j][k] = 0.f;

    auto compute = [&](int ch) {
        const uint32_t stgA = smBase + (uint32_t)((ch % NSTG) * 2 * TSZ) * 4;
        const uint32_t stgW = stgA + (uint32_t)TSZ * 4;
#pragma unroll
        for (int ks = 0; ks < 2; ks++) {
            const int k0 = ks * 8;
            uint32_t af[4][4], bf4[2][4];
#pragma unroll
            for (int mt = 0; mt < 4; mt++)
                ldsm_x4(af[mt],
                        stgA + (uint32_t)(aOffW + mt * 16 * SSTR + k0) * 4);
#pragma unroll
            for (int np = 0; np < 2; np++)
                ldsm_x4(bf4[np],
                        stgW + (uint32_t)(bOffW + np * 16 * SSTR + k0) * 4);
#pragma unroll
            for (int mt = 0; mt < 4; mt++)
#pragma unroll
                for (int nt = 0; nt < 4; nt++)
                    mma_tf32(acc[mt][nt], af[mt], &bf4[nt >> 1][(nt & 1) * 2]);
        }
    };

    for (int ch = 0; ch < nch; ch += 2) {
        CP_WAIT1();
        __syncthreads();

        if (ch + 3 < nch) issue(ch + 3);
        CP_COMMIT();
        compute(ch);

        if (ch + 4 < nch) issue(ch + 4);
        CP_COMMIT();
        compute(ch + 1);
    }

    // ---- epilogue (validated) ----
#pragma unroll
    for (int mt = 0; mt < 4; mt++) {
#pragma unroll
        for (int nt = 0; nt < 4; nt++) {
#pragma unroll
            for (int hi = 0; hi < 2; hi++) {
                int r = rowBase + wm * 64 + mt * 16 + g + hi * 8;
                int c = colBase + wn * 32 + nt * 8 + 2 * t4;
                float v0 = acc[mt][nt][hi * 2 + 0];
                float v1 = acc[mt][nt][hi * 2 + 1];
                if (MODE == 0) {
                    int b  = r >> 9;
                    int ss = r & 511;
#pragma unroll
                    for (int q = 0; q < 2; q++) {
                        int e = c + q;
                        float v = (q ? v1 : v0) + bias[e];
                        int h = e / 192, rr = e - h * 192;
                        int w = rr >> 6, dh = rr & 63;
                        int n = ss * Hc + h;
                        g_qkv[(((size_t)n * 3 + w) * Bc + b) * DHc + dh] =
                            __uint_as_float(f2tf32(v));
                    }
                } else {
                    float2* dst = (float2*)(Cout + (size_t)r * N + c);
                    *dst = make_float2(v0, v1);
                }
            }
        }
    }
}

// ---------------------------------------------------------------- attention
// (unchanged — validated)
#define QP 68
#define PP 132
#define OFF_KS (128 * QP)
#define OFF_VT (2 * 128 * QP)
#define ATTN_FLOATS (OFF_VT + 64 * PP)
#define SMEM_ATTN (ATTN_FLOATS * 4)

__global__ __launch_bounds__(256, 1) void attn_kernel()
{
    extern __shared__ float sm[];
    uint32_t* Qs = (uint32_t*)sm;
    uint32_t* Ks = (uint32_t*)sm + OFF_KS;
    uint32_t* Vt = (uint32_t*)sm + OFF_VT;
    float*    Ps = sm;

    const int n   = blockIdx.x;
    const int tid = threadIdx.x;
    const int lane = tid & 31;
    const int warp = tid >> 5;
    const int wm = warp & 1;
    const int wn = warp >> 1;
    const int g  = lane >> 2;
    const int t4 = lane & 3;

    const uint32_t* qb = (const uint32_t*)(g_qkv + (size_t)n * 3 * Bc * DHc);
    const uint32_t* kb = qb + Bc * DHc;
    const uint32_t* vb = kb + Bc * DHc;

#pragma unroll
    for (int it = 0; it < 32; it++) {
        int idx = tid + it * 256;
        int r  = idx >> 6;
        int dh = idx & 63;
        Qs[r * QP + dh] = qb[idx];
        Ks[r * QP + dh] = kb[idx];
        Vt[dh * PP + r] = vb[idx];
    }
    __syncthreads();

    float acc[4][4][4];
#pragma unroll
    for (int i = 0; i < 4; i++)
#pragma unroll
        for (int j = 0; j < 4; j++)
#pragma unroll
            for (int k = 0; k < 4; k++) acc[i][j][k] = 0.f;

#pragma unroll
    for (int ks = 0; ks < 8; ks++) {
        const int k0 = ks * 8;
        uint32_t af[4][4], bf[4][2];
#pragma unroll
        for (int mt = 0; mt < 4; mt++) {
            int r0 = wm * 64 + mt * 16 + g;
            af[mt][0] = Qs[(r0)     * QP + k0 + t4];
            af[mt][1] = Qs[(r0 + 8) * QP + k0 + t4];
            af[mt][2] = Qs[(r0)     * QP + k0 + t4 + 4];
            af[mt][3] = Qs[(r0 + 8) * QP + k0 + t4 + 4];
        }
#pragma unroll
        for (int nt = 0; nt < 4; nt++) {
            int c0 = wn * 32 + nt * 8 + g;
            bf[nt][0] = Ks[c0 * QP + k0 + t4];
            bf[nt][1] = Ks[c0 * QP + k0 + t4 + 4];
        }
#pragma unroll
        for (int mt = 0; mt < 4; mt++)
#pragma unroll
            for (int nt = 0; nt < 4; nt++)
                mma_tf32(acc[mt][nt], af[mt], bf[nt]);
    }
    __syncthreads();

    const float scale = 0.125f;
#pragma unroll
    for (int mt = 0; mt < 4; mt++)
#pragma unroll
        for (int nt = 0; nt < 4; nt++)
#pragma unroll
            for (int hi = 0; hi < 2; hi++) {
                int r = wm * 64 + mt * 16 + g + hi * 8;
                int c = wn * 32 + nt * 8 + 2 * t4;
#pragma unroll
                for (int q = 0; q < 2; q++) {
                    float s = acc[mt][nt][hi * 2 + q] * scale;
                    if (c + q <= r) s = -10000.0f;
                    Ps[r * PP + c + q] = s;
                }
            }
    __syncthreads();

    for (int r = warp; r < 128; r += 8) {
        float v0 = Ps[r * PP + lane];
        float v1 = Ps[r * PP + lane + 32];
        float v2 = Ps[r * PP + lane + 64];
        float v3 = Ps[r * PP + lane + 96];
        float mx = fmaxf(fmaxf(v0, v1), fmaxf(v2, v3));
#pragma unroll
        for (int o = 16; o > 0; o >>= 1)
            mx = fmaxf(mx, __shfl_xor_sync(0xffffffffu, mx, o));
        float e0 = __expf(v0 - mx), e1 = __expf(v1 - mx);
        float e2 = __expf(v2 - mx), e3 = __expf(v3 - mx);
        float sum = e0 + e1 + e2 + e3;
#pragma unroll
        for (int o = 16; o > 0; o >>= 1)
            sum += __shfl_xor_sync(0xffffffffu, sum, o);
        float inv = 1.0f / sum;
        Ps[r * PP + lane]      = __uint_as_float(f2tf32(e0 * inv));
        Ps[r * PP + lane + 32] = __uint_as_float(f2tf32(e1 * inv));
        Ps[r * PP + lane + 64] = __uint_as_float(f2tf32(e2 * inv));
        Ps[r * PP + lane + 96] = __uint_as_float(f2tf32(e3 * inv));
    }
    __syncthreads();

    const uint32_t* Pu = (const uint32_t*)Ps;
    float acc2[4][2][4];
#pragma unroll
    for (int i = 0; i < 4; i++)
#pragma unroll
        for (int j = 0; j < 2; j++)
#pragma unroll
            for (int k = 0; k < 4; k++) acc2[i][j][k] = 0.f;

#pragma unroll
    for (int ks = 0; ks < 16; ks++) {
        const int k0 = ks * 8;
        uint32_t af[4][4], bf[2][2];
#pragma unroll
        for (int mt = 0; mt < 4; mt++) {
            int r0 = wm * 64 + mt * 16 + g;
            af[mt][0] = Pu[(r0)     * PP + k0 + t4];
            af[mt][1] = Pu[(r0 + 8) * PP + k0 + t4];
            af[mt][2] = Pu[(r0)     * PP + k0 + t4 + 4];
            af[mt][3] = Pu[(r0 + 8) * PP + k0 + t4 + 4];
        }
#pragma unroll
        for (int nt = 0; nt < 2; nt++) {
            int c0 = wn * 16 + nt * 8 + g;
            bf[nt][0] = Vt[c0 * PP + k0 + t4];
            bf[nt][1] = Vt[c0 * PP + k0 + t4 + 4];
        }
#pragma unroll
        for (int mt = 0; mt < 4; mt++)
#pragma unroll
            for (int nt = 0; nt < 2; nt++)
                mma_tf32(acc2[mt][nt], af[mt], bf[nt]);
    }

    const int s = n / Hc;
    const int h = n - s * Hc;
#pragma unroll
    for (int mt = 0; mt < 4; mt++)
#pragma unroll
        for (int nt = 0; nt < 2; nt++)
#pragma unroll
            for (int hi = 0; hi < 2; hi++) {
                int b  = wm * 64 + mt * 16 + g + hi * 8;
                int dh = wn * 16 + nt * 8 + 2 * t4;
                float2* dst = (float2*)(g_ctx +
                    ((size_t)b * Sc + s) * Dc + h * 64 + dh);
                *dst = make_float2(
                    __uint_as_float(f2tf32(acc2[mt][nt][hi * 2 + 0])),
                    __uint_as_float(f2tf32(acc2[mt][nt][hi * 2 + 1])));
            }
}

// ----------------------------------------------------------------
extern "C" void kernel_launch(void* const* d_in, const int* in_sizes, int n_in,
                              void* d_out, int out_size)
{
    const float* X       = (const float*)d_in[0];
    const float* W_qkv   = (const float*)d_in[1];
    const float* b_qkv   = (const float*)d_in[2];
    const float* W_dense = (const float*)d_in[3];
    const float* b_dense = (const float*)d_in[4];
    float* out = (float*)d_out;
    (void)in_sizes; (void)n_in;

    cudaFuncSetAttribute(gemm_mma<0>,
                         cudaFuncAttributeMaxDynamicSharedMemorySize, SMEM_GEMM);
    cudaFuncSetAttribute(gemm_mma<1>,
                         cudaFuncAttributeMaxDynamicSharedMemorySize, SMEM_GEMM);
    cudaFuncSetAttribute(attn_kernel,
                         cudaFuncAttributeMaxDynamicSharedMemorySize, SMEM_ATTN);

    // 0) one-time tf32 rounding passes
    {
        int n4x = NTOK * Dc / 4;
        prep_cvt<<<(n4x + 255) / 256, 256>>>((const float4*)X, n4x, 0);
        int n4q = E3 * Dc / 4;
        prep_cvt<<<(n4q + 255) / 256, 256>>>((const float4*)W_qkv, n4q, 1);
        int n4d = Dc * Dc / 4;
        prep_cvt<<<(n4d + 255) / 256, 256>>>((const float4*)W_dense, n4d, 2);
    }

    // 1) QKV = tf32(X) @ tf32(W_qkv)^T + bias -> g_qkv (tf32 bits)
    gemm_mma<0><<<dim3(E3 / 128, NTOK / 128), 256, SMEM_GEMM>>>(
        b_qkv, nullptr, Dc, E3);

    // 2) attention
    attn_kernel<<<NH, 256, SMEM_ATTN>>>();

    // 3) out = ctx @ tf32(W_dense)^T
    gemm_mma<1><<<dim3(Dc / 128, NTOK / 128), 256, SMEM_GEMM>>>(
        nullptr, out, Dc, Dc);

    // 4) tail: reference returns (out, b_dense)
    long long tail = (long long)out_size - (long long)NTOK * Dc;
    if (tail > 0) {
        if (tail > Dc) tail = Dc;
        cudaMemcpyAsync(out + (size_t)NTOK * Dc, b_dense,
                        (size_t)tail * sizeof(float),
                        cudaMemcpyDeviceToDevice, 0);
    }
}

// round 17
// speedup vs baseline: 1.4115x; 1.0335x over previous
#include <cuda_runtime.h>
#include <cstdint>

// ---------------------------------------------------------------- constants
#define Bc   128
#define Sc   512
#define Dc   768
#define Hc   12
#define DHc  64
#define NTOK (Bc * Sc)    // 65536
#define NH   (Sc * Hc)    // 6144
#define E3   (3 * Dc)     // 2304

// Scratch (allocation-free rule -> device globals)
__device__ float g_qkv[(size_t)NH * 3 * Bc * DHc];   // [n][qkv][b][dh], tf32 bits
__device__ float g_ctx[(size_t)NTOK * Dc];           // [b][s][d], tf32 bits
__device__ float g_Xc[(size_t)NTOK * Dc];            // tf32(X)
__device__ float g_Wq[(size_t)E3 * Dc];              // tf32(W_qkv)
__device__ float g_Wd[(size_t)Dc * Dc];              // tf32(W_dense)

// ---------------------------------------------------------------- helpers
__device__ __forceinline__ uint32_t f2tf32(float x) {
    uint32_t r;
    asm("cvt.rna.tf32.f32 %0, %1;" : "=r"(r) : "f"(x));
    return r;
}

__device__ __forceinline__ void mma_tf32(float* c, const uint32_t* a,
                                         const uint32_t* b)
{
    asm volatile(
        "mma.sync.aligned.m16n8k8.row.col.f32.tf32.tf32.f32 "
        "{%0,%1,%2,%3}, {%4,%5,%6,%7}, {%8,%9}, {%0,%1,%2,%3};"
        : "+f"(c[0]), "+f"(c[1]), "+f"(c[2]), "+f"(c[3])
        : "r"(a[0]), "r"(a[1]), "r"(a[2]), "r"(a[3]),
          "r"(b[0]), "r"(b[1]));
}

__device__ __forceinline__ void ldsm_x4(uint32_t* r, uint32_t addr) {
    asm volatile(
        "ldmatrix.sync.aligned.m8n8.x4.shared.b16 {%0,%1,%2,%3}, [%4];"
        : "=r"(r[0]), "=r"(r[1]), "=r"(r[2]), "=r"(r[3]) : "r"(addr));
}

__device__ __forceinline__ uint32_t smem_u32(const void* p) {
    uint32_t a;
    asm("{ .reg .u64 t; cvta.to.shared.u64 t, %1; cvt.u32.u64 %0, t; }"
        : "=r"(a) : "l"(p));
    return a;
}
__device__ __forceinline__ void cp_async16(uint32_t dst, const void* src) {
    asm volatile("cp.async.cg.shared.global [%0], [%1], 16;"
                 :: "r"(dst), "l"(src));
}
#define CP_COMMIT() asm volatile("cp.async.commit_group;" ::: "memory")
#define CP_WAIT1()  asm volatile("cp.async.wait_group 1;" ::: "memory")

// ---------------------------------------------------------------- prep
__global__ __launch_bounds__(256) void prep_cvt(const float4* __restrict__ src,
                                                int n4, int which)
{
    float4* dst = (which == 0) ? (float4*)g_Xc
                : (which == 1) ? (float4*)g_Wq : (float4*)g_Wd;
    int i = blockIdx.x * blockDim.x + threadIdx.x;
    if (i < n4) {
        float4 v = src[i];
        v.x = __uint_as_float(f2tf32(v.x));
        v.y = __uint_as_float(f2tf32(v.y));
        v.z = __uint_as_float(f2tf32(v.z));
        v.w = __uint_as_float(f2tf32(v.w));
        dst[i] = v;
    }
}

// ---------------------------------------------------------------- tc GEMM
// C[M,N] = A[M,K] * W[N,K]^T; inputs pre-tf32-rounded.
// CTA 128x128, 256 threads (8 warps, 2x4, warp tile 64x32), BK=16.
// 5-stage cp.async ring, barrier every 2 chunks, ldmatrix.x4 fragment loads,
// ping-pong fragment double-buffer across the 4 ks-steps of each pair.
#define BK    16
#define SSTR  20
#define TSZ   (128 * SSTR)                 // 2560 words / tile (10KB)
#define NSTG  5
#define SMEM_GEMM (NSTG * 2 * TSZ * 4)     // 102400 B

template <int MODE>
__global__ __launch_bounds__(256, 2) void gemm_mma(
    const float* __restrict__ bias, float* __restrict__ Cout,
    int K, int N)
{
    extern __shared__ uint32_t dynsm[];    // [NSTG][2][TSZ] (A then W)

    const float* Ap = (MODE == 1) ? (const float*)g_ctx : (const float*)g_Xc;
    const float* Wp = (MODE == 1) ? (const float*)g_Wd  : (const float*)g_Wq;

    const int tid  = threadIdx.x;
    const int lane = tid & 31;
    const int warp = tid >> 5;
    const int wm   = warp & 1;
    const int wn   = warp >> 1;
    const int g    = lane >> 2;
    const int t4   = lane & 3;

    const int rowBase = blockIdx.y * 128;
    const int colBase = blockIdx.x * 128;

    const int lr = tid >> 1;
    const int lc = (tid & 1) * 8;

    const float* gA = Ap + (size_t)(rowBase + lr) * K + lc;
    const float* gW = Wp + (size_t)(colBase + lr) * K + lc;

    const uint32_t smBase = smem_u32(dynsm);
    const uint32_t sBase  = smBase + (uint32_t)(lr * SSTR + lc) * 4;

    // ldmatrix per-thread address offsets (words)
    const int aOffW = (wm * 64 + ((lane >> 3) & 1) * 8 + (lane & 7)) * SSTR
                    + (lane >> 4) * 4;
    const int bOffW = (wn * 32 + (lane >> 4) * 8 + (lane & 7)) * SSTR
                    + ((lane >> 3) & 1) * 4;

    const int nch = K / BK;   // 48 (even)

    auto issue = [&](int ch) {
        int st = ch % NSTG;
        uint32_t da = sBase + (uint32_t)(st * 2 * TSZ) * 4;
        uint32_t dw = da + (uint32_t)TSZ * 4;
        const float* ga = gA + ch * BK;
        const float* gw = gW + ch * BK;
        cp_async16(da,      ga);
        cp_async16(da + 16, ga + 4);
        cp_async16(dw,      gw);
        cp_async16(dw + 16, gw + 4);
    };

#pragma unroll
    for (int p = 0; p < 3; p++) { issue(p); CP_COMMIT(); }

    float acc[4][4][4];
#pragma unroll
    for (int i = 0; i < 4; i++)
#pragma unroll
        for (int j = 0; j < 4; j++)
#pragma unroll
            for (int k = 0; k < 4; k++) acc[i][j][k] = 0.f;

    // load fragment set for (stage base address, k0)
    auto loadfr = [&](uint32_t stgA, int k0, uint32_t af[4][4],
                      uint32_t bf4[2][4]) {
        const uint32_t stgW = stgA + (uint32_t)TSZ * 4;
#pragma unroll
        for (int mt = 0; mt < 4; mt++)
            ldsm_x4(af[mt], stgA + (uint32_t)(aOffW + mt * 16 * SSTR + k0) * 4);
#pragma unroll
        for (int np = 0; np < 2; np++)
            ldsm_x4(bf4[np], stgW + (uint32_t)(bOffW + np * 16 * SSTR + k0) * 4);
    };

    auto mmastep = [&](uint32_t af[4][4], uint32_t bf4[2][4]) {
#pragma unroll
        for (int mt = 0; mt < 4; mt++)
#pragma unroll
            for (int nt = 0; nt < 4; nt++)
                mma_tf32(acc[mt][nt], af[mt], &bf4[nt >> 1][(nt & 1) * 2]);
    };

    for (int ch = 0; ch < nch; ch += 2) {
        CP_WAIT1();
        __syncthreads();

        const uint32_t stg0 = smBase + (uint32_t)((ch % NSTG) * 2 * TSZ) * 4;
        const uint32_t stg1 = smBase + (uint32_t)(((ch + 1) % NSTG) * 2 * TSZ) * 4;

        uint32_t af[2][4][4], bf[2][2][4];
        loadfr(stg0, 0, af[0], bf[0]);

        if (ch + 3 < nch) issue(ch + 3);
        CP_COMMIT();

        // 4 ks-steps across the pair: (stg0,k0=0/8), (stg1,k0=0/8)
#pragma unroll
        for (int s = 0; s < 4; s++) {
            if (s < 3) {
                uint32_t stgN = (s >= 1) ? stg1 : stg0;
                int k0N = ((s + 1) & 1) * 8;
                loadfr(stgN, k0N, af[(s + 1) & 1], bf[(s + 1) & 1]);
            }
            if (s == 1) {
                if (ch + 4 < nch) issue(ch + 4);
                CP_COMMIT();
            }
            mmastep(af[s & 1], bf[s & 1]);
        }
    }

    // ---- epilogue (validated) ----
#pragma unroll
    for (int mt = 0; mt < 4; mt++) {
#pragma unroll
        for (int nt = 0; nt < 4; nt++) {
#pragma unroll
            for (int hi = 0; hi < 2; hi++) {
                int r = rowBase + wm * 64 + mt * 16 + g + hi * 8;
                int c = colBase + wn * 32 + nt * 8 + 2 * t4;
                float v0 = acc[mt][nt][hi * 2 + 0];
                float v1 = acc[mt][nt][hi * 2 + 1];
                if (MODE == 0) {
                    int b  = r >> 9;
                    int ss = r & 511;
#pragma unroll
                    for (int q = 0; q < 2; q++) {
                        int e = c + q;
                        float v = (q ? v1 : v0) + bias[e];
                        int h = e / 192, rr = e - h * 192;
                        int w = rr >> 6, dh = rr & 63;
                        int n = ss * Hc + h;
                        g_qkv[(((size_t)n * 3 + w) * Bc + b) * DHc + dh] =
                            __uint_as_float(f2tf32(v));
                    }
                } else {
                    float2* dst = (float2*)(Cout + (size_t)r * N + c);
                    *dst = make_float2(v0, v1);
                }
            }
        }
    }
}

// ---------------------------------------------------------------- attention
// (unchanged — validated)
#define QP 68
#define PP 132
#define OFF_KS (128 * QP)
#define OFF_VT (2 * 128 * QP)
#define ATTN_FLOATS (OFF_VT + 64 * PP)
#define SMEM_ATTN (ATTN_FLOATS * 4)

__global__ __launch_bounds__(256, 1) void attn_kernel()
{
    extern __shared__ float sm[];
    uint32_t* Qs = (uint32_t*)sm;
    uint32_t* Ks = (uint32_t*)sm + OFF_KS;
    uint32_t* Vt = (uint32_t*)sm + OFF_VT;
    float*    Ps = sm;

    const int n   = blockIdx.x;
    const int tid = threadIdx.x;
    const int lane = tid & 31;
    const int warp = tid >> 5;
    const int wm = warp & 1;
    const int wn = warp >> 1;
    const int g  = lane >> 2;
    const int t4 = lane & 3;

    const uint32_t* qb = (const uint32_t*)(g_qkv + (size_t)n * 3 * Bc * DHc);
    const uint32_t* kb = qb + Bc * DHc;
    const uint32_t* vb = kb + Bc * DHc;

#pragma unroll
    for (int it = 0; it < 32; it++) {
        int idx = tid + it * 256;
        int r  = idx >> 6;
        int dh = idx & 63;
        Qs[r * QP + dh] = qb[idx];
        Ks[r * QP + dh] = kb[idx];
        Vt[dh * PP + r] = vb[idx];
    }
    __syncthreads();

    float acc[4][4][4];
#pragma unroll
    for (int i = 0; i < 4; i++)
#pragma unroll
        for (int j = 0; j < 4; j++)
#pragma unroll
            for (int k = 0; k < 4; k++) acc[i][j][k] = 0.f;

#pragma unroll
    for (int ks = 0; ks < 8; ks++) {
        const int k0 = ks * 8;
        uint32_t af[4][4], bf[4][2];
#pragma unroll
        for (int mt = 0; mt < 4; mt++) {
            int r0 = wm * 64 + mt * 16 + g;
            af[mt][0] = Qs[(r0)     * QP + k0 + t4];
            af[mt][1] = Qs[(r0 + 8) * QP + k0 + t4];
            af[mt][2] = Qs[(r0)     * QP + k0 + t4 + 4];
            af[mt][3] = Qs[(r0 + 8) * QP + k0 + t4 + 4];
        }
#pragma unroll
        for (int nt = 0; nt < 4; nt++) {
            int c0 = wn * 32 + nt * 8 + g;
            bf[nt][0] = Ks[c0 * QP + k0 + t4];
            bf[nt][1] = Ks[c0 * QP + k0 + t4 + 4];
        }
#pragma unroll
        for (int mt = 0; mt < 4; mt++)
#pragma unroll
            for (int nt = 0; nt < 4; nt++)
                mma_tf32(acc[mt][nt], af[mt], bf[nt]);
    }
    __syncthreads();

    const float scale = 0.125f;
#pragma unroll
    for (int mt = 0; mt < 4; mt++)
#pragma unroll
        for (int nt = 0; nt < 4; nt++)
#pragma unroll
            for (int hi = 0; hi < 2; hi++) {
                int r = wm * 64 + mt * 16 + g + hi * 8;
                int c = wn * 32 + nt * 8 + 2 * t4;
#pragma unroll
                for (int q = 0; q < 2; q++) {
                    float s = acc[mt][nt][hi * 2 + q] * scale;
                    if (c + q <= r) s = -10000.0f;
                    Ps[r * PP + c + q] = s;
                }
            }
    __syncthreads();

    for (int r = warp; r < 128; r += 8) {
        float v0 = Ps[r * PP + lane];
        float v1 = Ps[r * PP + lane + 32];
        float v2 = Ps[r * PP + lane + 64];
        float v3 = Ps[r * PP + lane + 96];
        float mx = fmaxf(fmaxf(v0, v1), fmaxf(v2, v3));
#pragma unroll
        for (int o = 16; o > 0; o >>= 1)
            mx = fmaxf(mx, __shfl_xor_sync(0xffffffffu, mx, o));
        float e0 = __expf(v0 - mx), e1 = __expf(v1 - mx);
        float e2 = __expf(v2 - mx), e3 = __expf(v3 - mx);
        float sum = e0 + e1 + e2 + e3;
#pragma unroll
        for (int o = 16; o > 0; o >>= 1)
            sum += __shfl_xor_sync(0xffffffffu, sum, o);
        float inv = 1.0f / sum;
        Ps[r * PP + lane]      = __uint_as_float(f2tf32(e0 * inv));
        Ps[r * PP + lane + 32] = __uint_as_float(f2tf32(e1 * inv));
        Ps[r * PP + lane + 64] = __uint_as_float(f2tf32(e2 * inv));
        Ps[r * PP + lane + 96] = __uint_as_float(f2tf32(e3 * inv));
    }
    __syncthreads();

    const uint32_t* Pu = (const uint32_t*)Ps;
    float acc2[4][2][4];
#pragma unroll
    for (int i = 0; i < 4; i++)
#pragma unroll
        for (int j = 0; j < 2; j++)
#pragma unroll
            for (int k = 0; k < 4; k++) acc2[i][j][k] = 0.f;

#pragma unroll
    for (int ks = 0; ks < 16; ks++) {
        const int k0 = ks * 8;
        uint32_t af[4][4], bf[2][2];
#pragma unroll
        for (int mt = 0; mt < 4; mt++) {
            int r0 = wm * 64 + mt * 16 + g;
            af[mt][0] = Pu[(r0)     * PP + k0 + t4];
            af[mt][1] = Pu[(r0 + 8) * PP + k0 + t4];
            af[mt][2] = Pu[(r0)     * PP + k0 + t4 + 4];
            af[mt][3] = Pu[(r0 + 8) * PP + k0 + t4 + 4];
        }
#pragma unroll
        for (int nt = 0; nt < 2; nt++) {
            int c0 = wn * 16 + nt * 8 + g;
            bf[nt][0] = Vt[c0 * PP + k0 + t4];
            bf[nt][1] = Vt[c0 * PP + k0 + t4 + 4];
        }
#pragma unroll
        for (int mt = 0; mt < 4; mt++)
#pragma unroll
            for (int nt = 0; nt < 2; nt++)
                mma_tf32(acc2[mt][nt], af[mt], bf[nt]);
    }

    const int s = n / Hc;
    const int h = n - s * Hc;
#pragma unroll
    for (int mt = 0; mt < 4; mt++)
#pragma unroll
        for (int nt = 0; nt < 2; nt++)
#pragma unroll
            for (int hi = 0; hi < 2; hi++) {
                int b  = wm * 64 + mt * 16 + g + hi * 8;
                int dh = wn * 16 + nt * 8 + 2 * t4;
                float2* dst = (float2*)(g_ctx +
                    ((size_t)b * Sc + s) * Dc + h * 64 + dh);
                *dst = make_float2(
                    __uint_as_float(f2tf32(acc2[mt][nt][hi * 2 + 0])),
                    __uint_as_float(f2tf32(acc2[mt][nt][hi * 2 + 1])));
            }
}

// ----------------------------------------------------------------
extern "C" void kernel_launch(void* const* d_in, const int* in_sizes, int n_in,
                              void* d_out, int out_size)
{
    const float* X       = (const float*)d_in[0];
    const float* W_qkv   = (const float*)d_in[1];
    const float* b_qkv   = (const float*)d_in[2];
    const float* W_dense = (const float*)d_in[3];
    const float* b_dense = (const float*)d_in[4];
    float* out = (float*)d_out;
    (void)in_sizes; (void)n_in;

    cudaFuncSetAttribute(gemm_mma<0>,
                         cudaFuncAttributeMaxDynamicSharedMemorySize, SMEM_GEMM);
    cudaFuncSetAttribute(gemm_mma<1>,
                         cudaFuncAttributeMaxDynamicSharedMemorySize, SMEM_GEMM);
    cudaFuncSetAttribute(attn_kernel,
                         cudaFuncAttributeMaxDynamicSharedMemorySize, SMEM_ATTN);

    // 0) one-time tf32 rounding passes
    {
        int n4x = NTOK * Dc / 4;
        prep_cvt<<<(n4x + 255) / 256, 256>>>((const float4*)X, n4x, 0);
        int n4q = E3 * Dc / 4;
        prep_cvt<<<(n4q + 255) / 256, 256>>>((const float4*)W_qkv, n4q, 1);
        int n4d = Dc * Dc / 4;
        prep_cvt<<<(n4d + 255) / 256, 256>>>((const float4*)W_dense, n4d, 2);
    }

    // 1) QKV = tf32(X) @ tf32(W_qkv)^T + bias -> g_qkv (tf32 bits)
    gemm_mma<0><<<dim3(E3 / 128, NTOK / 128), 256, SMEM_GEMM>>>(
        b_qkv, nullptr, Dc, E3);

    // 2) attention
    attn_kernel<<<NH, 256, SMEM_ATTN>>>();

    // 3) out = ctx @ tf32(W_dense)^T
    gemm_mma<1><<<dim3(Dc / 128, NTOK / 128), 256, SMEM_GEMM>>>(
        nullptr, out, Dc, Dc);

    // 4) tail: reference returns (out, b_dense)
    long long tail = (long long)out_size - (long long)NTOK * Dc;
    if (tail > 0) {
        if (tail > Dc) tail = Dc;
        cudaMemcpyAsync(out + (size_t)NTOK * Dc, b_dense,
                        (size_t)tail * sizeof(float),
                        cudaMemcpyDeviceToDevice, 0);
    }
}